// round 12
// baseline (speedup 1.0000x reference)
#include <cuda_runtime.h>
#include <math.h>

#define MAXN 100000
#define MAXE 1600000
#define HDIM 64

// Scratch (__device__ globals; no allocation allowed)
__device__ __align__(256) float g_hs[(size_t)MAXN * HDIM];   // layer GEMM output
__device__ __align__(256) float g_buf[(size_t)MAXN * HDIM];  // layer output / next input
__device__ float g_dinv[MAXN];
__device__ int g_cnt[MAXN];        // in-degree histogram
__device__ int g_rowptr[MAXN + 1]; // CSR row offsets (by dst)
__device__ int g_cursor[MAXN];     // fill cursors
__device__ int2 g_cedge[MAXE];     // CSR entries: (src, bits(dinv[src]))
__device__ int g_btotal[512];      // per-block totals (+1 sentinel) for decoupled scan

// packed f32x2 ops (B300)
#define FMA2(d, a, b, c) \
    asm("fma.rn.f32x2 %0, %1, %2, %3;" : "=l"(d) : "l"(a), "l"(b), "l"(c))
#define ADD2(d, a, b) \
    asm("add.rn.f32x2 %0, %1, %2;" : "=l"(d) : "l"(a), "l"(b))
#define PACK2(d, f) \
    asm("mov.b64 %0, {%1, %1};" : "=l"(d) : "f"(f))

// ---------------- GEMM tile body (256 threads, 64 rows/tile) ----------------
template <int K, bool SCALE>
__device__ __forceinline__ void gemm_tile(const float* __restrict__ X,
                                          const float* __restrict__ W, int n, int tile,
                                          float* smem) {
    constexpr int KP = K + 4;
    float* sWt = smem;            // [64][KP] transposed W
    float* sX  = smem + 64 * KP;  // [64][K]
    int tid = threadIdx.x;

    for (int i = tid; i < K * 64; i += 256) {
        int k = i >> 6, c = i & 63;
        sWt[c * KP + k] = W[i];
    }
    int row0 = tile * 64;
    int nrows = n - row0; if (nrows > 64) nrows = 64;
    for (int i = tid; i < nrows * K; i += 256) sX[i] = X[(size_t)row0 * K + i];
    __syncthreads();

    int w = tid >> 5, lane = tid & 31;
    unsigned long long acc0[8], acc1[8];  // (even-k, odd-k) packed partial sums
#pragma unroll
    for (int r = 0; r < 8; r++) { acc0[r] = 0ull; acc1[r] = 0ull; }

    const ulonglong2* wt0 = (const ulonglong2*)(sWt + lane * KP);
    const ulonglong2* wt1 = (const ulonglong2*)(sWt + (lane + 32) * KP);
#pragma unroll 4
    for (int k4 = 0; k4 < K / 4; k4++) {
        ulonglong2 w0 = wt0[k4];
        ulonglong2 w1 = wt1[k4];
#pragma unroll
        for (int r = 0; r < 8; r++) {
            ulonglong2 xv = ((const ulonglong2*)(sX + (w * 8 + r) * K))[k4];
            FMA2(acc0[r], w0.x, xv.x, acc0[r]);
            FMA2(acc0[r], w0.y, xv.y, acc0[r]);
            FMA2(acc1[r], w1.x, xv.x, acc1[r]);
            FMA2(acc1[r], w1.y, xv.y, acc1[r]);
        }
    }

#pragma unroll
    for (int r = 0; r < 8; r++) {
        int row = row0 + w * 8 + r;
        if (row < n) {
            float sc = SCALE ? g_dinv[row] : 1.0f;
            float e0, o0, e1, o1;
            asm("mov.b64 {%0, %1}, %2;" : "=f"(e0), "=f"(o0) : "l"(acc0[r]));
            asm("mov.b64 {%0, %1}, %2;" : "=f"(e1), "=f"(o1) : "l"(acc1[r]));
            size_t o = (size_t)row * HDIM;
            g_hs[o + lane]      = (e0 + o0) * sc;
            g_hs[o + lane + 32] = (e1 + o1) * sc;
        }
    }
}

// ---------------- CSR roles (256-thread blocks) ----------------
__device__ __forceinline__ void hist_role(const int* __restrict__ dst, int E, int rb) {
    int base = rb * 2048 + threadIdx.x;
#pragma unroll
    for (int k = 0; k < 8; k++) {
        int e = base + k * 256;
        if (e < E) atomicAdd(&g_cnt[dst[e]], 1);
    }
}

// decoupled-lookback scan; safe at any grid size (blocks wait only on lower ids)
__device__ __forceinline__ void scan_role(int n, int E, int bid) {
    __shared__ int wsum[8];
    __shared__ int s_prefix;
    int tid = threadIdx.x, lane = tid & 31, w = tid >> 5;
    int i = bid * 256 + tid;
    int v = (i < n) ? g_cnt[i] : 0;
    int x = v;
#pragma unroll
    for (int off = 1; off < 32; off <<= 1) {
        int t = __shfl_up_sync(0xffffffffu, x, off);
        if (lane >= off) x += t;
    }
    if (lane == 31) wsum[w] = x;
    __syncthreads();
    if (tid < 8) {
        int s = wsum[tid];
#pragma unroll
        for (int off = 1; off < 8; off <<= 1) {
            int t = __shfl_up_sync(0xffu, s, off);
            if (tid >= off) s += t;
        }
        wsum[tid] = s;
    }
    __syncthreads();
    int incl = x + (w > 0 ? wsum[w - 1] : 0);
    if (tid == 0) {
        s_prefix = 0;
        atomicExch(&g_btotal[bid], wsum[7] + 1);  // sentinel +1 (0 == not ready)
    }
    __syncthreads();
    for (int p = tid; p < bid; p += 256) {
        int t;
        do { t = atomicAdd(&g_btotal[p], 0); } while (t == 0);
        atomicAdd_block(&s_prefix, t - 1);
    }
    __syncthreads();
    int prefix = s_prefix;
    if (i < n) {
        int r = prefix + incl - v;
        g_rowptr[i] = r;
        g_cursor[i] = r;
        g_dinv[i] = rsqrtf((float)v + 1.0f);
    }
    if (i == n) g_rowptr[n] = E;
}

__device__ __forceinline__ void fill_role(const int* __restrict__ src,
                                          const int* __restrict__ dst, int E, int rb) {
    int base = rb * 2048 + threadIdx.x;
#pragma unroll
    for (int k = 0; k < 8; k++) {
        int e = base + k * 256;
        if (e < E) {
            int d = dst[e], s = src[e];
            int pos = atomicAdd(&g_cursor[d], 1);
            g_cedge[pos] = make_int2(s, __float_as_int(g_dinv[s]));
        }
    }
}

// ---------------- fused launches: CSR role blocks + gemm1 tile blocks ----------------
__global__ __launch_bounds__(256) void fused1_kernel(const float* __restrict__ x,
                                                     const float* __restrict__ W1, int n, int E,
                                                     const int* __restrict__ dst,
                                                     int roleBlocks, int tileBase) {
    extern __shared__ float smem[];
    if ((int)blockIdx.x < roleBlocks) hist_role(dst, E, blockIdx.x);
    else gemm_tile<128, false>(x, W1, n, blockIdx.x - roleBlocks + tileBase, smem);
}

__global__ __launch_bounds__(256) void fused2_kernel(const float* __restrict__ x,
                                                     const float* __restrict__ W1, int n, int E,
                                                     int roleBlocks, int tileBase) {
    extern __shared__ float smem[];
    if ((int)blockIdx.x < roleBlocks) scan_role(n, E, blockIdx.x);
    else gemm_tile<128, false>(x, W1, n, blockIdx.x - roleBlocks + tileBase, smem);
}

__global__ __launch_bounds__(256) void fused3_kernel(const float* __restrict__ x,
                                                     const float* __restrict__ W1, int n, int E,
                                                     const int* __restrict__ src,
                                                     const int* __restrict__ dst,
                                                     int roleBlocks, int tileBase) {
    extern __shared__ float smem[];
    if ((int)blockIdx.x < roleBlocks) fill_role(src, dst, E, blockIdx.x);
    else gemm_tile<128, false>(x, W1, n, blockIdx.x - roleBlocks + tileBase, smem);
}

// layers 2/3 GEMM (dinv-scaled output)
__global__ __launch_bounds__(256) void gemm64_kernel(const float* __restrict__ W, int n) {
    extern __shared__ float smem[];
    gemm_tile<64, true>(g_buf, W, n, blockIdx.x, smem);
}

// ---------------- fused aggregate + LN + GELU (+ head) ----------------
// warp per node; lane covers cols {2*lane, 2*lane+1}; SSRC: apply dinv[src] per edge
template <bool SSRC>
__global__ __launch_bounds__(256) void agg_post_kernel(const float* __restrict__ b,
                                                       const float* __restrict__ g,
                                                       const float* __restrict__ be, int n, int last,
                                                       const float* __restrict__ Wh,
                                                       const float* __restrict__ bh,
                                                       float* __restrict__ out) {
    int w = threadIdx.x >> 5, lane = threadIdx.x & 31;
    int row = blockIdx.x * 8 + w;
    if (row >= n) return;

    const unsigned long long* hs2 = (const unsigned long long*)g_hs;
    size_t ro = (size_t)row * 32 + lane;
    unsigned long long self = hs2[ro];
    float dv = g_dinv[row];

    unsigned long long aE = 0ull, aO = 0ull;
    if (SSRC) {
        unsigned long long dvp; PACK2(dvp, dv);
        FMA2(aE, self, dvp, aE);     // h[row]*dv
    } else {
        ADD2(aE, aE, self);          // hs[row] already scaled
    }

    int beg = g_rowptr[row], end = g_rowptr[row + 1];
    for (int base = beg; base < end; base += 32) {
        int e = base + lane;
        int2 ev = (e < end) ? __ldg(&g_cedge[e]) : make_int2(0, 0);
        int cnt = end - base; if (cnt > 32) cnt = 32;
        int j = 0;
        for (; j + 2 <= cnt; j += 2) {
            int s0 = __shfl_sync(0xffffffffu, ev.x, j);
            int s1 = __shfl_sync(0xffffffffu, ev.x, j + 1);
            unsigned long long v0 = __ldg(hs2 + (size_t)s0 * 32 + lane);
            unsigned long long v1 = __ldg(hs2 + (size_t)s1 * 32 + lane);
            if (SSRC) {
                float f0 = __int_as_float(__shfl_sync(0xffffffffu, ev.y, j));
                float f1 = __int_as_float(__shfl_sync(0xffffffffu, ev.y, j + 1));
                unsigned long long p0, p1;
                PACK2(p0, f0); PACK2(p1, f1);
                FMA2(aE, v0, p0, aE);
                FMA2(aO, v1, p1, aO);
            } else {
                ADD2(aE, aE, v0);
                ADD2(aO, aO, v1);
            }
        }
        if (j < cnt) {
            int s0 = __shfl_sync(0xffffffffu, ev.x, j);
            unsigned long long v0 = __ldg(hs2 + (size_t)s0 * 32 + lane);
            if (SSRC) {
                float f0 = __int_as_float(__shfl_sync(0xffffffffu, ev.y, j));
                unsigned long long p0; PACK2(p0, f0);
                FMA2(aE, v0, p0, aE);
            } else {
                ADD2(aE, aE, v0);
            }
        }
    }

    unsigned long long at;
    ADD2(at, aE, aO);
    float a0, a1;
    asm("mov.b64 {%0, %1}, %2;" : "=f"(a0), "=f"(a1) : "l"(at));

    float2 bb = ((const float2*)b)[lane];
    float v0 = a0 * dv + bb.x;
    float v1 = a1 * dv + bb.y;

    float s = v0 + v1;
#pragma unroll
    for (int off = 16; off; off >>= 1) s += __shfl_xor_sync(0xffffffffu, s, off);
    float m = s * (1.0f / 64.0f);
    float d0 = v0 - m, d1 = v1 - m;
    float vv = d0 * d0 + d1 * d1;
#pragma unroll
    for (int off = 16; off; off >>= 1) vv += __shfl_xor_sync(0xffffffffu, vv, off);
    float rs = rsqrtf(vv * (1.0f / 64.0f) + 1e-5f);

    float2 gg = ((const float2*)g)[lane];
    float2 ee = ((const float2*)be)[lane];
    float y0 = d0 * rs * gg.x + ee.x;
    float y1 = d1 * rs * gg.y + ee.y;
    y0 = 0.5f * y0 * (1.0f + erff(y0 * 0.70710678118654752f));
    y1 = 0.5f * y1 * (1.0f + erff(y1 * 0.70710678118654752f));

    if (!last) {
        float2 yy; yy.x = y0; yy.y = y1;
        ((float2*)g_buf)[ro] = yy;
    } else {
        float2 wh = ((const float2*)Wh)[lane];
        float hsum = y0 * wh.x + y1 * wh.y;
#pragma unroll
        for (int off = 16; off; off >>= 1) hsum += __shfl_xor_sync(0xffffffffu, hsum, off);
        if (lane == 0) out[row] = hsum + bh[0];
    }
}

extern "C" void kernel_launch(void* const* d_in, const int* in_sizes, int n_in,
                              void* d_out, int out_size) {
    const float* x   = (const float*)d_in[0];
    const int*   ei  = (const int*)d_in[1];
    const float* W1  = (const float*)d_in[2];
    const float* b1  = (const float*)d_in[3];
    const float* g1  = (const float*)d_in[4];
    const float* be1 = (const float*)d_in[5];
    const float* W2  = (const float*)d_in[6];
    const float* b2  = (const float*)d_in[7];
    const float* g2  = (const float*)d_in[8];
    const float* be2 = (const float*)d_in[9];
    const float* W3  = (const float*)d_in[10];
    const float* b3  = (const float*)d_in[11];
    const float* g3  = (const float*)d_in[12];
    const float* be3 = (const float*)d_in[13];
    const float* Wh  = (const float*)d_in[14];
    const float* bh  = (const float*)d_in[15];
    float* out = (float*)d_out;

    int N = in_sizes[0] / 128;
    int E = in_sizes[1] / 2;
    const int* src = ei;
    const int* dst = ei + E;

    size_t sh128 = (size_t)(64 * 132 + 64 * 128) * sizeof(float);  // 66560 B
    size_t sh64  = (size_t)(64 * 68 + 64 * 64) * sizeof(float);    // 33792 B
    cudaFuncSetAttribute(fused1_kernel, cudaFuncAttributeMaxDynamicSharedMemorySize, (int)sh128);
    cudaFuncSetAttribute(fused2_kernel, cudaFuncAttributeMaxDynamicSharedMemorySize, (int)sh128);
    cudaFuncSetAttribute(fused3_kernel, cudaFuncAttributeMaxDynamicSharedMemorySize, (int)sh128);
    cudaFuncSetAttribute(gemm64_kernel, cudaFuncAttributeMaxDynamicSharedMemorySize, (int)sh64);

    int T  = (N + 63) / 64;       // gemm1 tiles (1563)
    int t1 = T / 3, t2 = T / 3, t3 = T - t1 - t2;
    int HB = (E + 2047) / 2048;   // hist/fill role blocks (782)
    int SCB = (N + 255) / 256;    // scan role blocks (391 <= 512)
    int ablocks = (N + 7) / 8;

    void* cnt_ptr = nullptr; void* btot_ptr = nullptr;
    cudaGetSymbolAddress(&cnt_ptr, g_cnt);
    cudaGetSymbolAddress(&btot_ptr, g_btotal);
    cudaMemsetAsync(cnt_ptr, 0, (size_t)N * sizeof(int));
    cudaMemsetAsync(btot_ptr, 0, 512 * sizeof(int));

    // CSR build overlapped with layer-1 GEMM (unscaled h)
    fused1_kernel<<<HB + t1, 256, sh128>>>(x, W1, N, E, dst, HB, 0);
    fused2_kernel<<<SCB + t2, 256, sh128>>>(x, W1, N, E, SCB, t1);
    fused3_kernel<<<HB + t3, 256, sh128>>>(x, W1, N, E, src, dst, HB, t1 + t2);
    agg_post_kernel<true><<<ablocks, 256>>>(b1, g1, be1, N, 0, nullptr, nullptr, nullptr);

    // layer 2 (K=64)
    gemm64_kernel<<<T, 256, sh64>>>(W2, N);
    agg_post_kernel<false><<<ablocks, 256>>>(b2, g2, be2, N, 0, nullptr, nullptr, nullptr);

    // layer 3 (K=64) + fused head
    gemm64_kernel<<<T, 256, sh64>>>(W3, N);
    agg_post_kernel<false><<<ablocks, 256>>>(b3, g3, be3, N, 1, Wh, bh, out);
}